// round 16
// baseline (speedup 1.0000x reference)
#include <cuda_runtime.h>
#include <cuda_bf16.h>
#include <math.h>

// ---------------------------------------------------------------------------
// B=1, C=64, H=W=64, N=4096, heads=8, dh=8, inner=64, hid_lc=32, hid_f=256.
// Activations fp32, [channel][pixel] layout.
// ---------------------------------------------------------------------------

constexpr int NPIX = 4096;

constexpr int OFF_QKV  = 0;                        // 192*N  raw qkv
constexpr int OFF_QKVM = OFF_QKV  + 192 * NPIX;    // 192*N  modulated qkv
constexpr int OFF_GAM  = OFF_QKVM + 192 * NPIX;    // 64*N
constexpr int OFF_BET  = OFF_GAM  + 64  * NPIX;    // 64*N
constexpr int OFF_INVL = OFF_BET  + 64  * NPIX;    // N
constexpr int OFF_MEAN = OFF_INVL + NPIX;          // [0]=mean
constexpr int OFF_KN   = OFF_MEAN + 8;             // [0..7] max||k||^2 per head
constexpr int OFF_AL   = OFF_MEAN + 64;            // 8 heads * N   l sums (atomic)
constexpr int OFF_ACC  = OFF_AL   + 8 * NPIX;      // 64 ch * N     acc sums (atomic)
constexpr int OFF_X2   = OFF_ACC  + 64 * NPIX;     // 64*N
constexpr int OFF_Y1   = OFF_X2   + 64  * NPIX;    // 256*N
constexpr int OFF_Y2   = OFF_Y1   + 256 * NPIX;    // 256*N
constexpr int TOTAL_F  = OFF_Y2   + 256 * NPIX;

__device__ float g_buf[TOTAL_F];

// ---------------- packed f32x2 / bf16 helpers --------------------------------
typedef unsigned long long u64;
__device__ __forceinline__ u64 pack2(float lo, float hi) {
    u64 r; asm("mov.b64 %0,{%1,%2};" : "=l"(r) : "f"(lo), "f"(hi)); return r;
}
__device__ __forceinline__ float2 unpack2(u64 v) {
    float2 r; asm("mov.b64 {%0,%1},%2;" : "=f"(r.x), "=f"(r.y) : "l"(v)); return r;
}
__device__ __forceinline__ u64 fma2(u64 a, u64 b, u64 c) {
    u64 d; asm("fma.rn.f32x2 %0,%1,%2,%3;" : "=l"(d) : "l"(a), "l"(b), "l"(c)); return d;
}
__device__ __forceinline__ float ex2f(float x) {
    float y; asm("ex2.approx.f32 %0,%1;" : "=f"(y) : "f"(x)); return y;
}
__device__ __forceinline__ unsigned bfpack(float lo, float hi) {
    __nv_bfloat162 t = __floats2bfloat162_rn(lo, hi);
    return *reinterpret_cast<unsigned*>(&t);
}
__device__ __forceinline__ float2 bfunpack(unsigned u) {
    __nv_bfloat162 t = *reinterpret_cast<__nv_bfloat162*>(&u);
    return __bfloat1622float2(t);
}
// m16n8k16 row.col bf16 MMA, fp32 accumulate (in-place C).
__device__ __forceinline__ void mma_bf16(float& c0, float& c1, float& c2, float& c3,
        unsigned a0, unsigned a1, unsigned a2, unsigned a3,
        unsigned b0, unsigned b1) {
    asm volatile(
        "mma.sync.aligned.m16n8k16.row.col.f32.bf16.bf16.f32 "
        "{%0,%1,%2,%3}, {%4,%5,%6,%7}, {%8,%9}, {%0,%1,%2,%3};\n"
        : "+f"(c0), "+f"(c1), "+f"(c2), "+f"(c3)
        : "r"(a0), "r"(a1), "r"(a2), "r"(a3), "r"(b0), "r"(b1));
}

// ---------------------------------------------------------------------------
// Prelude: one kernel, 275 CTAs.
//   bx <  192 : fused LN1 + QKV 1x1-conv GEMM
//   bx <  256 : lc1 -> lc2 -> gamma/beta GEMM for one 8x8 spatial tile
//   bx == 256 : avgpool3x3(1-luma)/9 + global mean
//   bx >= 257 : zero the AL/ACC atomic accumulators (18 CTAs, float4 stores)
// ---------------------------------------------------------------------------
__global__ void __launch_bounds__(256) prelude_kernel(
        const float* __restrict__ x, const float* __restrict__ luma,
        const float* __restrict__ ln1_w, const float* __restrict__ ln1_b,
        const float* __restrict__ qkv_w, const float* __restrict__ qkv_b,
        const float* __restrict__ w1, const float* __restrict__ b1,
        const float* __restrict__ w2, const float* __restrict__ b2,
        const float* __restrict__ gw, const float* __restrict__ gb,
        const float* __restrict__ bw, const float* __restrict__ bb) {
    const int bx = blockIdx.x;
    const int tid = threadIdx.x;

    if (bx >= 257) {  // ------------- zero AL/ACC (72*N floats) -------------
        float4* dst = (float4*)(g_buf + OFF_AL);
        int base = (bx - 257) * 4096 + tid;
#pragma unroll
        for (int q = 0; q < 16; q++)
            dst[base + q * 256] = make_float4(0.f, 0.f, 0.f, 0.f);
        return;
    }

    if (bx < 192) {  // ---------------- LN1 + QKV GEMM ----------------------
        __shared__ u64 ws2[8 * 64];
        __shared__ float wl[64], bl[64];
        const int row0 = (bx >> 4) * 16;
        for (int i = tid; i < 512; i += 256) {
            int p = i >> 6, k = i & 63;
            ws2[i] = pack2(qkv_w[(row0 + 2 * p) * 64 + k], qkv_w[(row0 + 2 * p + 1) * 64 + k]);
        }
        if (tid < 64) { wl[tid] = ln1_w[tid]; bl[tid] = ln1_b[tid]; }
        __syncthreads();
        const int n = (bx & 15) * 256 + tid;
        float v[64];
        float s = 0.f;
#pragma unroll
        for (int c = 0; c < 64; c++) { v[c] = x[(c << 12) + n]; s += v[c]; }
        float mu = s * (1.f / 64.f);
        float ss = 0.f;
#pragma unroll
        for (int c = 0; c < 64; c++) { float d = v[c] - mu; ss = fmaf(d, d, ss); }
        float rs = rsqrtf(ss * (1.f / 64.f) + 1e-5f);
#pragma unroll
        for (int c = 0; c < 64; c++) v[c] = (v[c] - mu) * rs * wl[c] + bl[c];
        u64 acc[8];
#pragma unroll
        for (int p = 0; p < 8; p++) acc[p] = 0ULL;
#pragma unroll 8
        for (int k = 0; k < 64; k++) {
            u64 x2 = pack2(v[k], v[k]);
#pragma unroll
            for (int p = 0; p < 8; p++) acc[p] = fma2(ws2[p * 64 + k], x2, acc[p]);
        }
#pragma unroll
        for (int p = 0; p < 8; p++) {
            float2 a = unpack2(acc[p]);
            int r0 = row0 + 2 * p;
            g_buf[OFF_QKV + (r0 << 12) + n] = a.x + qkv_b[r0];
            g_buf[OFF_QKV + ((r0 + 1) << 12) + n] = a.y + qkv_b[r0 + 1];
        }
        return;
    }

    if (bx == 256) {  // ---------------- pool + mean ------------------------
        __shared__ float sm[256];
        float tot = 0.f;
        for (int q = 0; q < 16; q++) {
            int n = tid + q * 256;
            int y = n >> 6, xx = n & 63;
            float s = 0.f;
#pragma unroll
            for (int dy = -1; dy <= 1; dy++) {
                int iy = y + dy;
                if ((unsigned)iy < 64u) {
#pragma unroll
                    for (int dx = -1; dx <= 1; dx++) {
                        int ix = xx + dx;
                        if ((unsigned)ix < 64u) s += 1.0f - luma[iy * 64 + ix];
                    }
                }
            }
            s *= (1.0f / 9.0f);
            g_buf[OFF_INVL + n] = s;
            tot += s;
        }
        sm[tid] = tot;
        __syncthreads();
        for (int st = 128; st > 0; st >>= 1) {
            if (tid < st) sm[tid] += sm[tid + st];
            __syncthreads();
        }
        if (tid == 0) g_buf[OFF_MEAN] = sm[0] * (1.0f / 4096.0f);
        return;
    }

    // ---------------- lc1 -> lc2 -> gamma/beta for one 8x8 tile ------------
    __shared__ float lum[12][13];
    __shared__ float wl1[32][9];
    __shared__ float h1s[32][10][12];
    __shared__ float h2s[32][65];
    const int tile = bx - 192;
    const int ty0 = (tile >> 3) * 8, tx0 = (tile & 7) * 8;

    for (int i = tid; i < 144; i += 256) {
        int yy = i / 12, xx = i - yy * 12;
        int gy = ty0 + yy - 2, gx = tx0 + xx - 2;
        float v = 0.f;
        if ((unsigned)gy < 64u && (unsigned)gx < 64u) v = luma[gy * 64 + gx];
        lum[yy][xx] = v;
    }
    for (int i = tid; i < 288; i += 256) wl1[i / 9][i % 9] = w1[i];
    __syncthreads();

    for (int i = tid; i < 3200; i += 256) {
        int ic = i / 100, r = i - ic * 100;
        int yy = r / 10, xx = r - yy * 10;
        int gy = ty0 + yy - 1, gx = tx0 + xx - 1;
        float v = 0.f;
        if ((unsigned)gy < 64u && (unsigned)gx < 64u) {
            float a = b1[ic];
#pragma unroll
            for (int ky = 0; ky < 3; ky++)
#pragma unroll
                for (int kx = 0; kx < 3; kx++)
                    a = fmaf(wl1[ic][ky * 3 + kx], lum[yy + ky][xx + kx], a);
            v = fmaxf(a, 0.f);
        }
        h1s[ic][yy][xx] = v;
    }
    __syncthreads();

    {
        const int oc = tid >> 3, py = tid & 7;
        float acc[8];
        float bb2 = b2[oc];
#pragma unroll
        for (int o = 0; o < 8; o++) acc[o] = bb2;
        for (int ic = 0; ic < 32; ic++) {
            float c[3][10];
#pragma unroll
            for (int r = 0; r < 3; r++)
#pragma unroll
                for (int q = 0; q < 10; q++) c[r][q] = h1s[ic][py + r][q];
            const float* wr = w2 + (oc * 32 + ic) * 9;
#pragma unroll
            for (int ky = 0; ky < 3; ky++)
#pragma unroll
                for (int kx = 0; kx < 3; kx++) {
                    float wv = wr[ky * 3 + kx];
#pragma unroll
                    for (int o = 0; o < 8; o++) acc[o] = fmaf(wv, c[ky][kx + o], acc[o]);
                }
        }
#pragma unroll
        for (int o = 0; o < 8; o++) h2s[oc][py * 8 + o] = fmaxf(acc[o], 0.f);
    }
    __syncthreads();

    {
        const int px = tid & 63, grp = tid >> 6;
        const int py = px >> 3, pxc = px & 7;
        const int n = (ty0 + py) * 64 + tx0 + pxc;
        float hv[32];
#pragma unroll
        for (int ic = 0; ic < 32; ic++) hv[ic] = h2s[ic][px];
        const bool isg = grp < 2;
        const float* W = isg ? gw : bw;
        const float* bias = isg ? gb : bb;
        const int outoff = isg ? OFF_GAM : OFF_BET;
        const int r0 = (grp & 1) * 32;
#pragma unroll 4
        for (int r = 0; r < 32; r++) {
            const float* wr = W + (r0 + r) * 32;
            float a = bias[r0 + r];
#pragma unroll
            for (int ic = 0; ic < 32; ic++) a = fmaf(wr[ic], hv[ic], a);
            g_buf[outoff + ((r0 + r) << 12) + n] = a;
        }
    }
}

// ---------------------------------------------------------------------------
// Modulation of q,k + per-head max||k||^2. Grid (16, 16).
// ---------------------------------------------------------------------------
__global__ void __launch_bounds__(256) modulate_qk_kernel(const float* __restrict__ alpha_p) {
    const int by = blockIdx.y;
    const int n = blockIdx.x * 256 + threadIdx.x;
    const int h = by & 7;
    if (by < 8) {           // q
        const float qb = alpha_p[0] * (g_buf[OFF_INVL + n] - g_buf[OFF_MEAN]);
#pragma unroll
        for (int d = 0; d < 8; d++) {
            int c = h * 8 + d;
            float g = g_buf[OFF_GAM + (c << 12) + n];
            float bt = g_buf[OFF_BET + (c << 12) + n];
            g_buf[OFF_QKVM + (c << 12) + n] =
                fmaf(g, g_buf[OFF_QKV + (c << 12) + n], bt) + qb;
        }
    } else {                // k (+ norm)
        __shared__ float sm[256];
        float kn = 0.f;
#pragma unroll
        for (int d = 0; d < 8; d++) {
            int c = 64 + h * 8 + d;
            float g = g_buf[OFF_GAM + ((c - 64) << 12) + n];
            float bt = g_buf[OFF_BET + ((c - 64) << 12) + n];
            float k = fmaf(g, g_buf[OFF_QKV + (c << 12) + n], bt);
            g_buf[OFF_QKVM + (c << 12) + n] = k;
            kn = fmaf(k, k, kn);
        }
        sm[threadIdx.x] = kn;
        __syncthreads();
        for (int st = 128; st > 0; st >>= 1) {
            if (threadIdx.x < st) sm[threadIdx.x] = fmaxf(sm[threadIdx.x], sm[threadIdx.x + st]);
            __syncthreads();
        }
        if (threadIdx.x == 0)
            atomicMax((unsigned int*)&g_buf[OFF_KN + h], __float_as_uint(sm[0]));
    }
}

// v modulation. Grid (16, 8).
__global__ void __launch_bounds__(256) modulate_v_kernel() {
    const int h = blockIdx.y;
    const int n = blockIdx.x * 256 + threadIdx.x;
#pragma unroll
    for (int d = 0; d < 8; d++) {
        int c = 128 + h * 8 + d;
        float g = g_buf[OFF_GAM + ((c - 128) << 12) + n];
        float bt = g_buf[OFF_BET + ((c - 128) << 12) + n];
        g_buf[OFF_QKVM + (c << 12) + n] =
            fmaf(g, g_buf[OFF_QKV + (c << 12) + n], bt);
    }
}

// ---------------------------------------------------------------------------
// Tensor-core flash attention. mma.sync m16n8k16 bf16, split-bf16 precision,
// K pre-split hi/lo and V pre-packed to bf16x2 in smem at fill time (the
// conversions happen once per CTA, not once per warp per tile). Inner loop
// fragments are single 32-bit LDS. 8 key-splits merged via atomicAdd.
// Grid (32 qblk, 8 heads, 8 ksplit) = 2048 CTAs, 128 thr.
// ---------------------------------------------------------------------------
__global__ void __launch_bounds__(128) attn_kernel() {
    __shared__ __align__(16) unsigned khs[512 * 4];   // [key][dimpair] hi
    __shared__ __align__(16) unsigned kls[512 * 4];   // [key][dimpair] lo
    __shared__ __align__(16) unsigned vvs[8 * 256];   // [dim][keypair]
    const int h = blockIdx.y, z = blockIdx.z;
    const int n0 = blockIdx.x * 128;
    const int tid = threadIdx.x;
    const int lane = tid & 31, wid = tid >> 5;
    const int r = lane >> 2;
    const int cp = lane & 3;            // dim-pair / key-pair index
    const int cq = cp * 2;
    const float* qp = g_buf + OFF_QKVM + (h * 8) * NPIX;
    const float* kp = g_buf + OFF_QKVM + (64 + h * 8) * NPIX;
    const float* vp = g_buf + OFF_QKVM + (128 + h * 8) * NPIX;
    const float kn2 = g_buf[OFF_KN + h];
    const float sc = 0.35355339059327373f * 1.4426950408889634f;  // dh^-0.5 * log2(e)

    const int jt = z * 512;
    // K: split into hi/lo bf16x2 over dim pairs.
    for (int i = tid; i < 2048; i += 128) {
        int j = i & 511, dp = i >> 9;
        float k0 = kp[((dp * 2) << 12) + jt + j];
        float k1 = kp[((dp * 2 + 1) << 12) + jt + j];
        unsigned hh = bfpack(k0, k1);
        float2 hf = bfunpack(hh);
        khs[j * 4 + dp] = hh;
        kls[j * 4 + dp] = bfpack(k0 - hf.x, k1 - hf.y);
    }
    // V: bf16x2 over key pairs.
    for (int i = tid; i < 2048; i += 128) {
        int jp = i & 255, d = i >> 8;
        float2 vv = *(const float2*)(vp + (d << 12) + jt + jp * 2);
        vvs[d * 256 + jp] = bfpack(vv.x, vv.y);
    }

    // Per-warp queries: n0 + wid*32 + t*16 + {r, r+8}, dims {cq, cq+1}.
    unsigned qh[2][2], ql[2][2];
    float negM[2][2], lsum[2][2], o[2][4];
#pragma unroll
    for (int t = 0; t < 2; t++) {
        lsum[t][0] = 0.f; lsum[t][1] = 0.f;
        o[t][0] = 0.f; o[t][1] = 0.f; o[t][2] = 0.f; o[t][3] = 0.f;
#pragma unroll
        for (int hf = 0; hf < 2; hf++) {
            int n = n0 + wid * 32 + t * 16 + r + hf * 8;
            float q0 = qp[(cq << 12) + n] * sc;
            float q1 = qp[((cq + 1) << 12) + n] * sc;
            float qn = fmaf(q0, q0, q1 * q1);
            qn += __shfl_xor_sync(0xffffffffu, qn, 1);
            qn += __shfl_xor_sync(0xffffffffu, qn, 2);
            negM[t][hf] = -sqrtf(qn * kn2);     // >= any |score|; split-invariant
            unsigned hh = bfpack(q0, q1);
            float2 hhf = bfunpack(hh);
            qh[t][hf] = hh;
            ql[t][hf] = bfpack(q0 - hhf.x, q1 - hhf.y);
        }
    }
    __syncthreads();

    for (int kt = 0; kt < 32; kt++) {
        unsigned kh2[2], kl2[2];
#pragma unroll
        for (int g = 0; g < 2; g++) {
            int key = kt * 16 + g * 8 + r;
            kh2[g] = khs[key * 4 + cp];
            kl2[g] = kls[key * 4 + cp];
        }
        unsigned bv0 = vvs[r * 256 + kt * 8 + cp];
        unsigned bv1 = vvs[r * 256 + kt * 8 + 4 + cp];
#pragma unroll
        for (int t = 0; t < 2; t++) {
            float p[2][4];
#pragma unroll
            for (int g = 0; g < 2; g++) {
                float c0 = negM[t][0], c1 = negM[t][0];
                float c2 = negM[t][1], c3 = negM[t][1];
                // S1 = qh.kh + ql.kh ; S2 += qh.kl  -> S = q.k - ql.kl - M
                mma_bf16(c0, c1, c2, c3,
                         qh[t][0], qh[t][1], ql[t][0], ql[t][1], kh2[g], kh2[g]);
                mma_bf16(c0, c1, c2, c3,
                         qh[t][0], qh[t][1], 0u, 0u, kl2[g], 0u);
                p[g][0] = ex2f(c0); p[g][1] = ex2f(c1);
                p[g][2] = ex2f(c2); p[g][3] = ex2f(c3);
                lsum[t][0] += p[g][0] + p[g][1];
                lsum[t][1] += p[g][2] + p[g][3];
            }
            // C-frag of S == A-frag of P (FA2 identity)
            unsigned a0 = bfpack(p[0][0], p[0][1]);
            unsigned a1 = bfpack(p[0][2], p[0][3]);
            unsigned a2 = bfpack(p[1][0], p[1][1]);
            unsigned a3 = bfpack(p[1][2], p[1][3]);
            mma_bf16(o[t][0], o[t][1], o[t][2], o[t][3], a0, a1, a2, a3, bv0, bv1);
        }
    }

    float* al = g_buf + OFF_AL;
    float* ac = g_buf + OFF_ACC;
#pragma unroll
    for (int t = 0; t < 2; t++) {
        int nq = n0 + wid * 32 + t * 16 + r;
        float l0 = lsum[t][0];
        l0 += __shfl_xor_sync(0xffffffffu, l0, 1);
        l0 += __shfl_xor_sync(0xffffffffu, l0, 2);
        float l1 = lsum[t][1];
        l1 += __shfl_xor_sync(0xffffffffu, l1, 1);
        l1 += __shfl_xor_sync(0xffffffffu, l1, 2);
        if ((lane & 3) == 0) {
            atomicAdd(al + (h << 12) + nq, l0);
            atomicAdd(al + (h << 12) + nq + 8, l1);
        }
        atomicAdd(ac + ((h * 8 + cq) << 12) + nq, o[t][0]);
        atomicAdd(ac + ((h * 8 + cq + 1) << 12) + nq, o[t][1]);
        atomicAdd(ac + ((h * 8 + cq) << 12) + nq + 8, o[t][2]);
        atomicAdd(ac + ((h * 8 + cq + 1) << 12) + nq + 8, o[t][3]);
    }
}

// ---------------------------------------------------------------------------
// Fused combine (normalize by l) + projection GEMM (K=64) + residual.
// Grid (16, 32), 2 rows per CTA.
// ---------------------------------------------------------------------------
__global__ void __launch_bounds__(256) combineproj_kernel(
        const float* __restrict__ W, const float* __restrict__ bias,
        const float* __restrict__ xres) {
    __shared__ u64 ws2[64];
    const int row0 = blockIdx.y * 2;
    for (int i = threadIdx.x; i < 64; i += 256)
        ws2[i] = pack2(W[row0 * 64 + i], W[(row0 + 1) * 64 + i]);
    __syncthreads();
    const int n = blockIdx.x * 256 + threadIdx.x;
    const float* al = g_buf + OFF_AL;
    const float* ac = g_buf + OFF_ACC;
    float rL[8];
#pragma unroll
    for (int h = 0; h < 8; h++) rL[h] = 1.0f / (al[(h << 12) + n] + 1e-35f);
    u64 acc = 0ULL;
#pragma unroll 16
    for (int k = 0; k < 64; k++) {
        float a = ac[(k << 12) + n] * rL[k >> 3];
        acc = fma2(ws2[k], pack2(a, a), acc);
    }
    float2 v = unpack2(acc);
    g_buf[OFF_X2 + (row0 << 12) + n] = v.x + bias[row0] + xres[(row0 << 12) + n];
    g_buf[OFF_X2 + ((row0 + 1) << 12) + n] = v.y + bias[row0 + 1] + xres[((row0 + 1) << 12) + n];
}

// ---------------------------------------------------------------------------
// Fused per-pixel LayerNorm + 1x1-conv GEMM (K=64) for ffn1.
// ---------------------------------------------------------------------------
__global__ void __launch_bounds__(256) ln_gemm_kernel(
        const float* __restrict__ x, const float* __restrict__ lnw,
        const float* __restrict__ lnb, const float* __restrict__ W,
        const float* __restrict__ bias, float* __restrict__ Y) {
    __shared__ u64 ws2[8 * 64];
    __shared__ float wl[64], bl[64];
    const int row0 = blockIdx.y * 16;
    for (int i = threadIdx.x; i < 512; i += 256) {
        int p = i >> 6, k = i & 63;
        ws2[i] = pack2(W[(row0 + 2 * p) * 64 + k], W[(row0 + 2 * p + 1) * 64 + k]);
    }
    if (threadIdx.x < 64) { wl[threadIdx.x] = lnw[threadIdx.x]; bl[threadIdx.x] = lnb[threadIdx.x]; }
    __syncthreads();
    const int n = blockIdx.x * 256 + threadIdx.x;
    float v[64];
    float s = 0.f;
#pragma unroll
    for (int c = 0; c < 64; c++) { v[c] = x[(c << 12) + n]; s += v[c]; }
    float mu = s * (1.f / 64.f);
    float ss = 0.f;
#pragma unroll
    for (int c = 0; c < 64; c++) { float d = v[c] - mu; ss = fmaf(d, d, ss); }
    float rs = rsqrtf(ss * (1.f / 64.f) + 1e-5f);
#pragma unroll
    for (int c = 0; c < 64; c++) v[c] = (v[c] - mu) * rs * wl[c] + bl[c];
    u64 acc[8];
#pragma unroll
    for (int p = 0; p < 8; p++) acc[p] = 0ULL;
#pragma unroll 8
    for (int k = 0; k < 64; k++) {
        u64 x2 = pack2(v[k], v[k]);
#pragma unroll
        for (int p = 0; p < 8; p++) acc[p] = fma2(ws2[p * 64 + k], x2, acc[p]);
    }
#pragma unroll
    for (int p = 0; p < 8; p++) {
        float2 a = unpack2(acc[p]);
        int r0 = row0 + 2 * p;
        Y[(r0 << 12) + n] = a.x + bias[r0];
        Y[((r0 + 1) << 12) + n] = a.y + bias[r0 + 1];
    }
}

// ---------------------------------------------------------------------------
// Depthwise 3x3 conv + exact GELU, one CTA per channel, smem halo tile.
// ---------------------------------------------------------------------------
__global__ void __launch_bounds__(256) dwgelu_kernel(const float* __restrict__ w,
                                                     const float* __restrict__ b) {
    __shared__ float s[66 * 66];
    const int c = blockIdx.x;
    const int tid = threadIdx.x;
    const float* in = g_buf + OFF_Y1 + (c << 12);
    for (int i = tid; i < 66 * 66; i += 256) {
        int yy = i / 66, xx = i - yy * 66;
        int gy = yy - 1, gx = xx - 1;
        float v = 0.f;
        if ((unsigned)gy < 64u && (unsigned)gx < 64u) v = in[gy * 64 + gx];
        s[i] = v;
    }
    __syncthreads();
    float wv[9];
#pragma unroll
    for (int k = 0; k < 9; k++) wv[k] = w[c * 9 + k];
    float bb = b[c];
#pragma unroll 4
    for (int t = 0; t < 16; t++) {
        int n = tid + t * 256;
        int y = n >> 6, x = n & 63;
        float a = bb;
#pragma unroll
        for (int ky = 0; ky < 3; ky++)
#pragma unroll
            for (int kx = 0; kx < 3; kx++)
                a = fmaf(wv[ky * 3 + kx], s[(y + ky) * 66 + x + kx], a);
        g_buf[OFF_Y2 + (c << 12) + n] = 0.5f * a * (1.0f + erff(a * 0.7071067811865476f));
    }
}

// ---------------------------------------------------------------------------
// ffn2: 1x1 conv GEMM K=256 + residual (writes final output). Grid (16, 16),
// 4 rows per CTA.
// ---------------------------------------------------------------------------
__global__ void __launch_bounds__(256) ffn2_kernel(const float* __restrict__ W,
                                                   const float* __restrict__ bias,
                                                   float* __restrict__ Y) {
    __shared__ u64 ws2[2 * 256];
    const int row0 = blockIdx.y * 4;
    for (int i = threadIdx.x; i < 512; i += 256) {
        int p = i >> 8, k = i & 255;
        ws2[i] = pack2(W[(row0 + 2 * p) * 256 + k], W[(row0 + 2 * p + 1) * 256 + k]);
    }
    __syncthreads();
    const int n = blockIdx.x * 256 + threadIdx.x;
    u64 acc[2];
    acc[0] = 0ULL; acc[1] = 0ULL;
#pragma unroll 8
    for (int k = 0; k < 256; k++) {
        float xv = g_buf[OFF_Y2 + (k << 12) + n];
        u64 x2 = pack2(xv, xv);
        acc[0] = fma2(ws2[k], x2, acc[0]);
        acc[1] = fma2(ws2[256 + k], x2, acc[1]);
    }
#pragma unroll
    for (int p = 0; p < 2; p++) {
        float2 a = unpack2(acc[p]);
        int r0 = row0 + 2 * p;
        Y[(r0 << 12) + n] = a.x + bias[r0] + g_buf[OFF_X2 + (r0 << 12) + n];
        Y[((r0 + 1) << 12) + n] = a.y + bias[r0 + 1] + g_buf[OFF_X2 + ((r0 + 1) << 12) + n];
    }
}

// ---------------------------------------------------------------------------
// Launch
// ---------------------------------------------------------------------------
extern "C" void kernel_launch(void* const* d_in, const int* in_sizes, int n_in,
                              void* d_out, int out_size) {
    const float* x      = (const float*)d_in[0];
    const float* luma   = (const float*)d_in[1];
    const float* ln1_w  = (const float*)d_in[2];
    const float* ln1_b  = (const float*)d_in[3];
    const float* qkv_w  = (const float*)d_in[4];
    const float* qkv_b  = (const float*)d_in[5];
    const float* proj_w = (const float*)d_in[6];
    const float* proj_b = (const float*)d_in[7];
    const float* lc1_w  = (const float*)d_in[8];
    const float* lc1_b  = (const float*)d_in[9];
    const float* lc2_w  = (const float*)d_in[10];
    const float* lc2_b  = (const float*)d_in[11];
    const float* gam_w  = (const float*)d_in[12];
    const float* gam_b  = (const float*)d_in[13];
    const float* bet_w  = (const float*)d_in[14];
    const float* bet_b  = (const float*)d_in[15];
    const float* alpha  = (const float*)d_in[16];
    const float* ln2_w  = (const float*)d_in[17];
    const float* ln2_b  = (const float*)d_in[18];
    const float* ffn1_w = (const float*)d_in[19];
    const float* ffn1_b = (const float*)d_in[20];
    const float* dw_w   = (const float*)d_in[21];
    const float* dw_b   = (const float*)d_in[22];
    const float* ffn2_w = (const float*)d_in[23];
    const float* ffn2_b = (const float*)d_in[24];
    float* out = (float*)d_out;

    float* buf = nullptr;
    cudaGetSymbolAddress((void**)&buf, g_buf);

    prelude_kernel<<<275, 256>>>(x, luma, ln1_w, ln1_b, qkv_w, qkv_b,
                                 lc1_w, lc1_b, lc2_w, lc2_b,
                                 gam_w, gam_b, bet_w, bet_b);
    modulate_qk_kernel<<<dim3(16, 16), 256>>>(alpha);
    modulate_v_kernel<<<dim3(16, 8), 256>>>();
    attn_kernel<<<dim3(32, 8, 8), 128>>>();            // 4th -> profiled
    combineproj_kernel<<<dim3(16, 32), 256>>>(proj_w, proj_b, x);
    ln_gemm_kernel<<<dim3(16, 16), 256>>>(buf + OFF_X2, ln2_w, ln2_b, ffn1_w, ffn1_b, buf + OFF_Y1);
    dwgelu_kernel<<<256, 256>>>(dw_w, dw_b);
    ffn2_kernel<<<dim3(16, 16), 256>>>(ffn2_w, ffn2_b, out);
}

// round 17
// speedup vs baseline: 1.0840x; 1.0840x over previous
#include <cuda_runtime.h>
#include <cuda_bf16.h>
#include <math.h>

// ---------------------------------------------------------------------------
// B=1, C=64, H=W=64, N=4096, heads=8, dh=8, inner=64, hid_lc=32, hid_f=256.
// Activations fp32, [channel][pixel] layout.
// ---------------------------------------------------------------------------

constexpr int NPIX = 4096;

constexpr int OFF_QKV  = 0;                        // 192*N  raw qkv
constexpr int OFF_QKVM = OFF_QKV  + 192 * NPIX;    // 192*N  modulated qkv
constexpr int OFF_GAM  = OFF_QKVM + 192 * NPIX;    // 64*N
constexpr int OFF_BET  = OFF_GAM  + 64  * NPIX;    // 64*N
constexpr int OFF_INVL = OFF_BET  + 64  * NPIX;    // N
constexpr int OFF_MEAN = OFF_INVL + NPIX;          // [0]=mean
constexpr int OFF_KN   = OFF_MEAN + 8;             // [0..7] max||k||^2 per head
constexpr int OFF_AL   = OFF_MEAN + 64;            // 8 heads * N   l sums (atomic)
constexpr int OFF_ACC  = OFF_AL   + 8 * NPIX;      // 64 ch * N     acc sums (atomic)
constexpr int OFF_X2   = OFF_ACC  + 64 * NPIX;     // 64*N
constexpr int OFF_Y1   = OFF_X2   + 64  * NPIX;    // 256*N
constexpr int OFF_Y2   = OFF_Y1   + 256 * NPIX;    // 256*N
constexpr int TOTAL_F  = OFF_Y2   + 256 * NPIX;

__device__ float g_buf[TOTAL_F];

// ---------------- packed f32x2 / bf16 helpers --------------------------------
typedef unsigned long long u64;
__device__ __forceinline__ u64 pack2(float lo, float hi) {
    u64 r; asm("mov.b64 %0,{%1,%2};" : "=l"(r) : "f"(lo), "f"(hi)); return r;
}
__device__ __forceinline__ float2 unpack2(u64 v) {
    float2 r; asm("mov.b64 {%0,%1},%2;" : "=f"(r.x), "=f"(r.y) : "l"(v)); return r;
}
__device__ __forceinline__ u64 fma2(u64 a, u64 b, u64 c) {
    u64 d; asm("fma.rn.f32x2 %0,%1,%2,%3;" : "=l"(d) : "l"(a), "l"(b), "l"(c)); return d;
}
__device__ __forceinline__ float ex2f(float x) {
    float y; asm("ex2.approx.f32 %0,%1;" : "=f"(y) : "f"(x)); return y;
}
__device__ __forceinline__ unsigned bfpack(float lo, float hi) {
    __nv_bfloat162 t = __floats2bfloat162_rn(lo, hi);
    return *reinterpret_cast<unsigned*>(&t);
}
__device__ __forceinline__ float2 bfunpack(unsigned u) {
    __nv_bfloat162 t = *reinterpret_cast<__nv_bfloat162*>(&u);
    return __bfloat1622float2(t);
}
// m16n8k16 row.col bf16 MMA, fp32 accumulate (in-place C).
__device__ __forceinline__ void mma_bf16(float& c0, float& c1, float& c2, float& c3,
        unsigned a0, unsigned a1, unsigned a2, unsigned a3,
        unsigned b0, unsigned b1) {
    asm volatile(
        "mma.sync.aligned.m16n8k16.row.col.f32.bf16.bf16.f32 "
        "{%0,%1,%2,%3}, {%4,%5,%6,%7}, {%8,%9}, {%0,%1,%2,%3};\n"
        : "+f"(c0), "+f"(c1), "+f"(c2), "+f"(c3)
        : "r"(a0), "r"(a1), "r"(a2), "r"(a3), "r"(b0), "r"(b1));
}

// ---------------------------------------------------------------------------
// Prelude: one kernel, 275 CTAs.
//   bx <  192 : fused LN1 + QKV 1x1-conv GEMM
//   bx <  256 : lc1 -> lc2 -> gamma/beta GEMM for one 8x8 spatial tile
//   bx == 256 : avgpool3x3(1-luma)/9 + global mean
//   bx >= 257 : zero the AL/ACC atomic accumulators (18 CTAs, float4 stores)
// ---------------------------------------------------------------------------
__global__ void __launch_bounds__(256) prelude_kernel(
        const float* __restrict__ x, const float* __restrict__ luma,
        const float* __restrict__ ln1_w, const float* __restrict__ ln1_b,
        const float* __restrict__ qkv_w, const float* __restrict__ qkv_b,
        const float* __restrict__ w1, const float* __restrict__ b1,
        const float* __restrict__ w2, const float* __restrict__ b2,
        const float* __restrict__ gw, const float* __restrict__ gb,
        const float* __restrict__ bw, const float* __restrict__ bb) {
    const int bx = blockIdx.x;
    const int tid = threadIdx.x;

    if (bx >= 257) {  // ------------- zero AL/ACC (72*N floats) -------------
        float4* dst = (float4*)(g_buf + OFF_AL);
        int base = (bx - 257) * 4096 + tid;
#pragma unroll
        for (int q = 0; q < 16; q++)
            dst[base + q * 256] = make_float4(0.f, 0.f, 0.f, 0.f);
        return;
    }

    if (bx < 192) {  // ---------------- LN1 + QKV GEMM ----------------------
        __shared__ u64 ws2[8 * 64];
        __shared__ float wl[64], bl[64];
        const int row0 = (bx >> 4) * 16;
        for (int i = tid; i < 512; i += 256) {
            int p = i >> 6, k = i & 63;
            ws2[i] = pack2(qkv_w[(row0 + 2 * p) * 64 + k], qkv_w[(row0 + 2 * p + 1) * 64 + k]);
        }
        if (tid < 64) { wl[tid] = ln1_w[tid]; bl[tid] = ln1_b[tid]; }
        __syncthreads();
        const int n = (bx & 15) * 256 + tid;
        float v[64];
        float s = 0.f;
#pragma unroll
        for (int c = 0; c < 64; c++) { v[c] = x[(c << 12) + n]; s += v[c]; }
        float mu = s * (1.f / 64.f);
        float ss = 0.f;
#pragma unroll
        for (int c = 0; c < 64; c++) { float d = v[c] - mu; ss = fmaf(d, d, ss); }
        float rs = rsqrtf(ss * (1.f / 64.f) + 1e-5f);
#pragma unroll
        for (int c = 0; c < 64; c++) v[c] = (v[c] - mu) * rs * wl[c] + bl[c];
        u64 acc[8];
#pragma unroll
        for (int p = 0; p < 8; p++) acc[p] = 0ULL;
#pragma unroll 8
        for (int k = 0; k < 64; k++) {
            u64 x2 = pack2(v[k], v[k]);
#pragma unroll
            for (int p = 0; p < 8; p++) acc[p] = fma2(ws2[p * 64 + k], x2, acc[p]);
        }
#pragma unroll
        for (int p = 0; p < 8; p++) {
            float2 a = unpack2(acc[p]);
            int r0 = row0 + 2 * p;
            g_buf[OFF_QKV + (r0 << 12) + n] = a.x + qkv_b[r0];
            g_buf[OFF_QKV + ((r0 + 1) << 12) + n] = a.y + qkv_b[r0 + 1];
        }
        return;
    }

    if (bx == 256) {  // ---------------- pool + mean ------------------------
        __shared__ float sm[256];
        float tot = 0.f;
        for (int q = 0; q < 16; q++) {
            int n = tid + q * 256;
            int y = n >> 6, xx = n & 63;
            float s = 0.f;
#pragma unroll
            for (int dy = -1; dy <= 1; dy++) {
                int iy = y + dy;
                if ((unsigned)iy < 64u) {
#pragma unroll
                    for (int dx = -1; dx <= 1; dx++) {
                        int ix = xx + dx;
                        if ((unsigned)ix < 64u) s += 1.0f - luma[iy * 64 + ix];
                    }
                }
            }
            s *= (1.0f / 9.0f);
            g_buf[OFF_INVL + n] = s;
            tot += s;
        }
        sm[tid] = tot;
        __syncthreads();
        for (int st = 128; st > 0; st >>= 1) {
            if (tid < st) sm[tid] += sm[tid + st];
            __syncthreads();
        }
        if (tid == 0) g_buf[OFF_MEAN] = sm[0] * (1.0f / 4096.0f);
        return;
    }

    // ---------------- lc1 -> lc2 -> gamma/beta for one 8x8 tile ------------
    __shared__ float lum[12][13];
    __shared__ float wl1[32][9];
    __shared__ float h1s[32][10][12];
    __shared__ float h2s[32][65];
    const int tile = bx - 192;
    const int ty0 = (tile >> 3) * 8, tx0 = (tile & 7) * 8;

    for (int i = tid; i < 144; i += 256) {
        int yy = i / 12, xx = i - yy * 12;
        int gy = ty0 + yy - 2, gx = tx0 + xx - 2;
        float v = 0.f;
        if ((unsigned)gy < 64u && (unsigned)gx < 64u) v = luma[gy * 64 + gx];
        lum[yy][xx] = v;
    }
    for (int i = tid; i < 288; i += 256) wl1[i / 9][i % 9] = w1[i];
    __syncthreads();

    for (int i = tid; i < 3200; i += 256) {
        int ic = i / 100, r = i - ic * 100;
        int yy = r / 10, xx = r - yy * 10;
        int gy = ty0 + yy - 1, gx = tx0 + xx - 1;
        float v = 0.f;
        if ((unsigned)gy < 64u && (unsigned)gx < 64u) {
            float a = b1[ic];
#pragma unroll
            for (int ky = 0; ky < 3; ky++)
#pragma unroll
                for (int kx = 0; kx < 3; kx++)
                    a = fmaf(wl1[ic][ky * 3 + kx], lum[yy + ky][xx + kx], a);
            v = fmaxf(a, 0.f);
        }
        h1s[ic][yy][xx] = v;
    }
    __syncthreads();

    {
        const int oc = tid >> 3, py = tid & 7;
        float acc[8];
        float bb2 = b2[oc];
#pragma unroll
        for (int o = 0; o < 8; o++) acc[o] = bb2;
        for (int ic = 0; ic < 32; ic++) {
            float c[3][10];
#pragma unroll
            for (int r = 0; r < 3; r++)
#pragma unroll
                for (int q = 0; q < 10; q++) c[r][q] = h1s[ic][py + r][q];
            const float* wr = w2 + (oc * 32 + ic) * 9;
#pragma unroll
            for (int ky = 0; ky < 3; ky++)
#pragma unroll
                for (int kx = 0; kx < 3; kx++) {
                    float wv = wr[ky * 3 + kx];
#pragma unroll
                    for (int o = 0; o < 8; o++) acc[o] = fmaf(wv, c[ky][kx + o], acc[o]);
                }
        }
#pragma unroll
        for (int o = 0; o < 8; o++) h2s[oc][py * 8 + o] = fmaxf(acc[o], 0.f);
    }
    __syncthreads();

    {
        const int px = tid & 63, grp = tid >> 6;
        const int py = px >> 3, pxc = px & 7;
        const int n = (ty0 + py) * 64 + tx0 + pxc;
        float hv[32];
#pragma unroll
        for (int ic = 0; ic < 32; ic++) hv[ic] = h2s[ic][px];
        const bool isg = grp < 2;
        const float* W = isg ? gw : bw;
        const float* bias = isg ? gb : bb;
        const int outoff = isg ? OFF_GAM : OFF_BET;
        const int r0 = (grp & 1) * 32;
#pragma unroll 4
        for (int r = 0; r < 32; r++) {
            const float* wr = W + (r0 + r) * 32;
            float a = bias[r0 + r];
#pragma unroll
            for (int ic = 0; ic < 32; ic++) a = fmaf(wr[ic], hv[ic], a);
            g_buf[outoff + ((r0 + r) << 12) + n] = a;
        }
    }
}

// ---------------------------------------------------------------------------
// Modulation of q,k,v + per-head max||k||^2, single launch. Grid (16, 24).
// ---------------------------------------------------------------------------
__global__ void __launch_bounds__(256) modulate_kernel(const float* __restrict__ alpha_p) {
    const int by = blockIdx.y;
    const int n = blockIdx.x * 256 + threadIdx.x;
    const int h = by & 7;
    if (by < 8) {           // q
        const float qb = alpha_p[0] * (g_buf[OFF_INVL + n] - g_buf[OFF_MEAN]);
#pragma unroll
        for (int d = 0; d < 8; d++) {
            int c = h * 8 + d;
            float g = g_buf[OFF_GAM + (c << 12) + n];
            float bt = g_buf[OFF_BET + (c << 12) + n];
            g_buf[OFF_QKVM + (c << 12) + n] =
                fmaf(g, g_buf[OFF_QKV + (c << 12) + n], bt) + qb;
        }
    } else if (by < 16) {   // k (+ norm)
        __shared__ float sm[256];
        float kn = 0.f;
#pragma unroll
        for (int d = 0; d < 8; d++) {
            int c = 64 + h * 8 + d;
            float g = g_buf[OFF_GAM + ((c - 64) << 12) + n];
            float bt = g_buf[OFF_BET + ((c - 64) << 12) + n];
            float k = fmaf(g, g_buf[OFF_QKV + (c << 12) + n], bt);
            g_buf[OFF_QKVM + (c << 12) + n] = k;
            kn = fmaf(k, k, kn);
        }
        sm[threadIdx.x] = kn;
        __syncthreads();
        for (int st = 128; st > 0; st >>= 1) {
            if (threadIdx.x < st) sm[threadIdx.x] = fmaxf(sm[threadIdx.x], sm[threadIdx.x + st]);
            __syncthreads();
        }
        if (threadIdx.x == 0)
            atomicMax((unsigned int*)&g_buf[OFF_KN + h], __float_as_uint(sm[0]));
    } else {                // v
#pragma unroll
        for (int d = 0; d < 8; d++) {
            int c = 128 + h * 8 + d;
            float g = g_buf[OFF_GAM + ((c - 128) << 12) + n];
            float bt = g_buf[OFF_BET + ((c - 128) << 12) + n];
            g_buf[OFF_QKVM + (c << 12) + n] =
                fmaf(g, g_buf[OFF_QKV + (c << 12) + n], bt);
        }
    }
}

// ---------------------------------------------------------------------------
// Tensor-core flash attention (exact R15 winner: 56.0us). mma.sync m16n8k16
// bf16, split-bf16 for QK^T precision (S = q.k - ql.kl), fixed Cauchy-Schwarz
// bound folded into the accumulator init, P (bf16) @ V via the FA2
// C-frag == A-frag identity. 8 key-splits merged via atomicAdd.
// Grid (32 qblk, 8 heads, 8 ksplit) = 2048 CTAs, 128 thr.
// ---------------------------------------------------------------------------
constexpr int KSP = 10;    // ks row pitch (floats)
constexpr int VSP = 522;   // vs row pitch (floats)

__global__ void __launch_bounds__(128) attn_kernel() {
    __shared__ __align__(16) float ks[512 * KSP];   // [j][d]
    __shared__ __align__(16) float vs[8 * VSP];     // [d][j]
    const int h = blockIdx.y, z = blockIdx.z;
    const int n0 = blockIdx.x * 128;
    const int tid = threadIdx.x;
    const int lane = tid & 31, wid = tid >> 5;
    const int r = lane >> 2;            // row / key / dim index (frag-dependent)
    const int cq = (lane & 3) * 2;      // column pair index
    const float* qp = g_buf + OFF_QKVM + (h * 8) * NPIX;
    const float* kp = g_buf + OFF_QKVM + (64 + h * 8) * NPIX;
    const float* vp = g_buf + OFF_QKVM + (128 + h * 8) * NPIX;
    const float kn2 = g_buf[OFF_KN + h];
    const float sc = 0.35355339059327373f * 1.4426950408889634f;  // dh^-0.5 * log2(e)

    const int jt = z * 512;
    for (int i = tid; i < 4096; i += 128) {
        int j = i & 511, d = i >> 9;
        float kv = kp[(d << 12) + jt + j];
        float vv = vp[(d << 12) + jt + j];
        ks[j * KSP + d] = kv;
        vs[d * VSP + j] = vv;
    }

    // Per-warp queries: n0 + wid*32 + t*16 + {r, r+8}, dims {cq, cq+1}.
    unsigned qh[2][2], ql[2][2];
    float negM[2][2], lsum[2][2], o[2][4];
#pragma unroll
    for (int t = 0; t < 2; t++) {
        lsum[t][0] = 0.f; lsum[t][1] = 0.f;
        o[t][0] = 0.f; o[t][1] = 0.f; o[t][2] = 0.f; o[t][3] = 0.f;
#pragma unroll
        for (int hf = 0; hf < 2; hf++) {
            int n = n0 + wid * 32 + t * 16 + r + hf * 8;
            float q0 = qp[(cq << 12) + n] * sc;
            float q1 = qp[((cq + 1) << 12) + n] * sc;
            float qn = fmaf(q0, q0, q1 * q1);
            qn += __shfl_xor_sync(0xffffffffu, qn, 1);
            qn += __shfl_xor_sync(0xffffffffu, qn, 2);
            negM[t][hf] = -sqrtf(qn * kn2);     // >= any |score|; split-invariant
            unsigned hh = bfpack(q0, q1);
            float2 hhf = bfunpack(hh);
            qh[t][hf] = hh;
            ql[t][hf] = bfpack(q0 - hhf.x, q1 - hhf.y);
        }
    }
    __syncthreads();

    for (int kt = 0; kt < 32; kt++) {
        // K fragments (split hi/lo): key = kt*16 + g*8 + r, dims cq,cq+1
        unsigned kh2[2], kl2[2];
#pragma unroll
        for (int g = 0; g < 2; g++) {
            float2 kf = *(const float2*)&ks[(kt * 16 + g * 8 + r) * KSP + cq];
            unsigned hh = bfpack(kf.x, kf.y);
            float2 hf = bfunpack(hh);
            kh2[g] = hh;
            kl2[g] = bfpack(kf.x - hf.x, kf.y - hf.y);
        }
        // V fragment: keys kt*16 + cq, cq+1 (+8), dim r
        unsigned bv0, bv1;
        {
            int kb = kt * 16 + cq;
            float2 v0 = *(const float2*)&vs[r * VSP + kb];
            float2 v1 = *(const float2*)&vs[r * VSP + kb + 8];
            bv0 = bfpack(v0.x, v0.y);
            bv1 = bfpack(v1.x, v1.y);
        }
#pragma unroll
        for (int t = 0; t < 2; t++) {
            float p[2][4];
#pragma unroll
            for (int g = 0; g < 2; g++) {
                float c0 = negM[t][0], c1 = negM[t][0];
                float c2 = negM[t][1], c3 = negM[t][1];
                // S1 = qh.kh + ql.kh ; S2 += qh.kl  -> S = q.k - ql.kl - M
                mma_bf16(c0, c1, c2, c3,
                         qh[t][0], qh[t][1], ql[t][0], ql[t][1], kh2[g], kh2[g]);
                mma_bf16(c0, c1, c2, c3,
                         qh[t][0], qh[t][1], 0u, 0u, kl2[g], 0u);
                p[g][0] = ex2f(c0); p[g][1] = ex2f(c1);
                p[g][2] = ex2f(c2); p[g][3] = ex2f(c3);
                lsum[t][0] += p[g][0] + p[g][1];
                lsum[t][1] += p[g][2] + p[g][3];
            }
            // C-frag of S == A-frag of P (FA2 identity)
            unsigned a0 = bfpack(p[0][0], p[0][1]);
            unsigned a1 = bfpack(p[0][2], p[0][3]);
            unsigned a2 = bfpack(p[1][0], p[1][1]);
            unsigned a3 = bfpack(p[1][2], p[1][3]);
            mma_bf16(o[t][0], o[t][1], o[t][2], o[t][3], a0, a1, a2, a3, bv0, bv1);
        }
    }

    float* al = g_buf + OFF_AL;
    float* ac = g_buf + OFF_ACC;
#pragma unroll
    for (int t = 0; t < 2; t++) {
        int nq = n0 + wid * 32 + t * 16 + r;
        float l0 = lsum[t][0];
        l0 += __shfl_xor_sync(0xffffffffu, l0, 1);
        l0 += __shfl_xor_sync(0xffffffffu, l0, 2);
        float l1 = lsum[t][1];
        l1 += __shfl_xor_sync(0xffffffffu, l1, 1);
        l1 += __shfl_xor_sync(0xffffffffu, l1, 2);
        if ((lane & 3) == 0) {
            atomicAdd(al + (h << 12) + nq, l0);
            atomicAdd(al + (h << 12) + nq + 8, l1);
        }
        atomicAdd(ac + ((h * 8 + cq) << 12) + nq, o[t][0]);
        atomicAdd(ac + ((h * 8 + cq + 1) << 12) + nq, o[t][1]);
        atomicAdd(ac + ((h * 8 + cq) << 12) + nq + 8, o[t][2]);
        atomicAdd(ac + ((h * 8 + cq + 1) << 12) + nq + 8, o[t][3]);
    }
}

// ---------------------------------------------------------------------------
// Fused combine (normalize by l) + projection GEMM (K=64) + residual.
// Grid (16, 32), 2 rows per CTA.
// ---------------------------------------------------------------------------
__global__ void __launch_bounds__(256) combineproj_kernel(
        const float* __restrict__ W, const float* __restrict__ bias,
        const float* __restrict__ xres) {
    __shared__ u64 ws2[64];
    const int row0 = blockIdx.y * 2;
    for (int i = threadIdx.x; i < 64; i += 256)
        ws2[i] = pack2(W[row0 * 64 + i], W[(row0 + 1) * 64 + i]);
    __syncthreads();
    const int n = blockIdx.x * 256 + threadIdx.x;
    const float* al = g_buf + OFF_AL;
    const float* ac = g_buf + OFF_ACC;
    float rL[8];
#pragma unroll
    for (int h = 0; h < 8; h++) rL[h] = 1.0f / (al[(h << 12) + n] + 1e-35f);
    u64 acc = 0ULL;
#pragma unroll 16
    for (int k = 0; k < 64; k++) {
        float a = ac[(k << 12) + n] * rL[k >> 3];
        acc = fma2(ws2[k], pack2(a, a), acc);
    }
    float2 v = unpack2(acc);
    g_buf[OFF_X2 + (row0 << 12) + n] = v.x + bias[row0] + xres[(row0 << 12) + n];
    g_buf[OFF_X2 + ((row0 + 1) << 12) + n] = v.y + bias[row0 + 1] + xres[((row0 + 1) << 12) + n];
}

// ---------------------------------------------------------------------------
// Fused per-pixel LayerNorm + 1x1-conv GEMM (K=64) for ffn1.
// ---------------------------------------------------------------------------
__global__ void __launch_bounds__(256) ln_gemm_kernel(
        const float* __restrict__ x, const float* __restrict__ lnw,
        const float* __restrict__ lnb, const float* __restrict__ W,
        const float* __restrict__ bias, float* __restrict__ Y) {
    __shared__ u64 ws2[8 * 64];
    __shared__ float wl[64], bl[64];
    const int row0 = blockIdx.y * 16;
    for (int i = threadIdx.x; i < 512; i += 256) {
        int p = i >> 6, k = i & 63;
        ws2[i] = pack2(W[(row0 + 2 * p) * 64 + k], W[(row0 + 2 * p + 1) * 64 + k]);
    }
    if (threadIdx.x < 64) { wl[threadIdx.x] = lnw[threadIdx.x]; bl[threadIdx.x] = lnb[threadIdx.x]; }
    __syncthreads();
    const int n = blockIdx.x * 256 + threadIdx.x;
    float v[64];
    float s = 0.f;
#pragma unroll
    for (int c = 0; c < 64; c++) { v[c] = x[(c << 12) + n]; s += v[c]; }
    float mu = s * (1.f / 64.f);
    float ss = 0.f;
#pragma unroll
    for (int c = 0; c < 64; c++) { float d = v[c] - mu; ss = fmaf(d, d, ss); }
    float rs = rsqrtf(ss * (1.f / 64.f) + 1e-5f);
#pragma unroll
    for (int c = 0; c < 64; c++) v[c] = (v[c] - mu) * rs * wl[c] + bl[c];
    u64 acc[8];
#pragma unroll
    for (int p = 0; p < 8; p++) acc[p] = 0ULL;
#pragma unroll 8
    for (int k = 0; k < 64; k++) {
        u64 x2 = pack2(v[k], v[k]);
#pragma unroll
        for (int p = 0; p < 8; p++) acc[p] = fma2(ws2[p * 64 + k], x2, acc[p]);
    }
#pragma unroll
    for (int p = 0; p < 8; p++) {
        float2 a = unpack2(acc[p]);
        int r0 = row0 + 2 * p;
        Y[(r0 << 12) + n] = a.x + bias[r0];
        Y[((r0 + 1) << 12) + n] = a.y + bias[r0 + 1];
    }
}

// ---------------------------------------------------------------------------
// Depthwise 3x3 conv + exact GELU, one CTA per channel, smem halo tile.
// ---------------------------------------------------------------------------
__global__ void __launch_bounds__(256) dwgelu_kernel(const float* __restrict__ w,
                                                     const float* __restrict__ b) {
    __shared__ float s[66 * 66];
    const int c = blockIdx.x;
    const int tid = threadIdx.x;
    const float* in = g_buf + OFF_Y1 + (c << 12);
    for (int i = tid; i < 66 * 66; i += 256) {
        int yy = i / 66, xx = i - yy * 66;
        int gy = yy - 1, gx = xx - 1;
        float v = 0.f;
        if ((unsigned)gy < 64u && (unsigned)gx < 64u) v = in[gy * 64 + gx];
        s[i] = v;
    }
    __syncthreads();
    float wv[9];
#pragma unroll
    for (int k = 0; k < 9; k++) wv[k] = w[c * 9 + k];
    float bb = b[c];
#pragma unroll 4
    for (int t = 0; t < 16; t++) {
        int n = tid + t * 256;
        int y = n >> 6, x = n & 63;
        float a = bb;
#pragma unroll
        for (int ky = 0; ky < 3; ky++)
#pragma unroll
            for (int kx = 0; kx < 3; kx++)
                a = fmaf(wv[ky * 3 + kx], s[(y + ky) * 66 + x + kx], a);
        g_buf[OFF_Y2 + (c << 12) + n] = 0.5f * a * (1.0f + erff(a * 0.7071067811865476f));
    }
}

// ---------------------------------------------------------------------------
// ffn2: 1x1 conv GEMM K=256 + residual (writes final output). Grid (16, 32),
// 2 rows per CTA (512 CTAs for latency hiding).
// ---------------------------------------------------------------------------
__global__ void __launch_bounds__(256) ffn2_kernel(const float* __restrict__ W,
                                                   const float* __restrict__ bias,
                                                   float* __restrict__ Y) {
    __shared__ u64 ws2[256];
    const int row0 = blockIdx.y * 2;
    for (int i = threadIdx.x; i < 256; i += 256)
        ws2[i] = pack2(W[row0 * 256 + i], W[(row0 + 1) * 256 + i]);
    __syncthreads();
    const int n = blockIdx.x * 256 + threadIdx.x;
    u64 acc = 0ULL;
#pragma unroll 16
    for (int k = 0; k < 256; k++) {
        float xv = g_buf[OFF_Y2 + (k << 12) + n];
        acc = fma2(ws2[k], pack2(xv, xv), acc);
    }
    float2 a = unpack2(acc);
    Y[(row0 << 12) + n] = a.x + bias[row0] + g_buf[OFF_X2 + (row0 << 12) + n];
    Y[((row0 + 1) << 12) + n] = a.y + bias[row0 + 1] + g_buf[OFF_X2 + ((row0 + 1) << 12) + n];
}

// ---------------------------------------------------------------------------
// Launch
// ---------------------------------------------------------------------------
extern "C" void kernel_launch(void* const* d_in, const int* in_sizes, int n_in,
                              void* d_out, int out_size) {
    const float* x      = (const float*)d_in[0];
    const float* luma   = (const float*)d_in[1];
    const float* ln1_w  = (const float*)d_in[2];
    const float* ln1_b  = (const float*)d_in[3];
    const float* qkv_w  = (const float*)d_in[4];
    const float* qkv_b  = (const float*)d_in[5];
    const float* proj_w = (const float*)d_in[6];
    const float* proj_b = (const float*)d_in[7];
    const float* lc1_w  = (const float*)d_in[8];
    const float* lc1_b  = (const float*)d_in[9];
    const float* lc2_w  = (const float*)d_in[10];
    const float* lc2_b  = (const float*)d_in[11];
    const float* gam_w  = (const float*)d_in[12];
    const float* gam_b  = (const float*)d_in[13];
    const float* bet_w  = (const float*)d_in[14];
    const float* bet_b  = (const float*)d_in[15];
    const float* alpha  = (const float*)d_in[16];
    const float* ln2_w  = (const float*)d_in[17];
    const float* ln2_b  = (const float*)d_in[18];
    const float* ffn1_w = (const float*)d_in[19];
    const float* ffn1_b = (const float*)d_in[20];
    const float* dw_w   = (const float*)d_in[21];
    const float* dw_b   = (const float*)d_in[22];
    const float* ffn2_w = (const float*)d_in[23];
    const float* ffn2_b = (const float*)d_in[24];
    float* out = (float*)d_out;

    float* buf = nullptr;
    cudaGetSymbolAddress((void**)&buf, g_buf);

    prelude_kernel<<<275, 256>>>(x, luma, ln1_w, ln1_b, qkv_w, qkv_b,
                                 lc1_w, lc1_b, lc2_w, lc2_b,
                                 gam_w, gam_b, bet_w, bet_b);
    modulate_kernel<<<dim3(16, 24), 256>>>(alpha);
    attn_kernel<<<dim3(32, 8, 8), 128>>>();
    combineproj_kernel<<<dim3(16, 32), 256>>>(proj_w, proj_b, x);
    ln_gemm_kernel<<<dim3(16, 16), 256>>>(buf + OFF_X2, ln2_w, ln2_b, ffn1_w, ffn1_b, buf + OFF_Y1);
    dwgelu_kernel<<<256, 256>>>(dw_w, dw_b);
    ffn2_kernel<<<dim3(16, 32), 256>>>(ffn2_w, ffn2_b, out);
}